// round 10
// baseline (speedup 1.0000x reference)
#include <cuda_runtime.h>
#include <cuda_fp16.h>
#include <math.h>
#include <stdint.h>

#define NB 4096
#define NF 256
#define NP 5000
#define NCHUNK 4
#define CHUNK_P 1280
#define NMTILE 32
#define NCTA (NMTILE * NCHUNK)        // 128
#define CAPC 16
#define IGNORE_INDEX 5554
#define AST 264                       // A smem row stride (halfs), 528B
#define BST 72                        // B smem row stride (halfs), 144B
#define A_BYTES (128 * AST * 2)       // 67584
#define B_STAGE (256 * BST * 2)       // 36864
#define NSTAGE 3
#define SM_META (A_BYTES + NSTAGE * B_STAGE)       // 178176
#define SM_RED  (SM_META + 4 * 128 * 4)            // 180224
#define SM_RLAB (SM_RED + 8 * 128 * 4)             // 184320
#define SMEM_TOTAL (SM_RLAB + CHUNK_P * 4)         // 189440
#define NI 40                         // 10 nt-tiles * 4 k-chunks
#define NTHREADS 256

// ---------------- static scratch ----------------
__device__ __align__(16) __half g_inh[NB * NF];
__device__ __align__(16) __half g_lih[NP * NF];
__device__ __align__(16) __half g_rlh[NP * NF];
__device__ float g_s_inst[NB * NCHUNK];
__device__ float g_s_reid[NB * NCHUNK];
__device__ int   g_pcnt[NB * NCHUNK];
__device__ float g_posx[NB * NCHUNK * CAPC];
__device__ float g_xt[NB];
__device__ float g_fc[NCTA];
__device__ float g_part[NMTILE][5];
__device__ int   g_ticket;

// ---------------- helpers ----------------
__device__ __forceinline__ uint32_t smem_u32(const void* p) {
    uint32_t a;
    asm("{ .reg .u64 t; cvta.to.shared.u64 t, %1; cvt.u32.u64 %0, t; }"
        : "=r"(a) : "l"(p));
    return a;
}
__device__ __forceinline__ void cp16(uint32_t dst, const void* src, int sz) {
    asm volatile("cp.async.cg.shared.global [%0], [%1], 16, %2;"
                 :: "r"(dst), "l"(src), "r"(sz) : "memory");
}
#define CP_COMMIT() asm volatile("cp.async.commit_group;" ::: "memory")
#define CP_WAIT2()  asm volatile("cp.async.wait_group 2;" ::: "memory")

__device__ __forceinline__ void ldmx4(uint32_t* r, uint32_t addr) {
    asm volatile("ldmatrix.sync.aligned.m8n8.x4.shared.b16 {%0,%1,%2,%3}, [%4];"
                 : "=r"(r[0]), "=r"(r[1]), "=r"(r[2]), "=r"(r[3]) : "r"(addr));
}
__device__ __forceinline__ void mma16(float* c, const uint32_t* a,
                                      uint32_t b0, uint32_t b1) {
    asm("mma.sync.aligned.m16n8k16.row.col.f32.f16.f16.f32 "
        "{%0,%1,%2,%3}, {%4,%5,%6,%7}, {%8,%9}, {%0,%1,%2,%3};"
        : "+f"(c[0]), "+f"(c[1]), "+f"(c[2]), "+f"(c[3])
        : "r"(a[0]), "r"(a[1]), "r"(a[2]), "r"(a[3]), "r"(b0), "r"(b1));
}

__device__ __forceinline__ uint2 cvt2(float4 v) {
    uint2 o;
    half2 lo = __floats2half2_rn(v.x, v.y);
    half2 hi = __floats2half2_rn(v.z, v.w);
    o.x = *(uint32_t*)&lo;
    o.y = *(uint32_t*)&hi;
    return o;
}

// ---------------------------------------------------------------------------
// K0: flat grid-stride f32->f16 convert + ticket reset + fc partials.
// ---------------------------------------------------------------------------
#define T0 (NB * NF / 4)
#define T1 (NP * NF / 4)
#define TTOT (T0 + 2 * T1)

__global__ void __launch_bounds__(256)
convert_kernel(const float* __restrict__ inp, const float* __restrict__ li,
               const float* __restrict__ rl, const int* __restrict__ roi_label)
{
    __shared__ float sred[8];
    int tid = threadIdx.x, wid = tid >> 5, lane = tid & 31;
    int idx = blockIdx.x * blockDim.x + tid;
    int stride = blockDim.x * gridDim.x;
    if (blockIdx.x == 0 && tid == 0) g_ticket = 0;

    for (int i = idx; i < TTOT; i += stride) {
        const float4* src;
        uint2* dst;
        int j;
        if (i < T0)           { src = (const float4*)inp; dst = (uint2*)g_inh; j = i; }
        else if (i < T0 + T1) { src = (const float4*)li;  dst = (uint2*)g_lih; j = i - T0; }
        else                  { src = (const float4*)rl;  dst = (uint2*)g_rlh; j = i - T0 - T1; }
        dst[j] = cvt2(src[j]);
    }

    if (blockIdx.x < NCTA) {
        int m0 = blockIdx.x * (NB / NCTA);
        float acc = 0.0f;
        for (int r = wid; r < NB / NCTA; r += 8) {
            int m = m0 + r;
            int t = roi_label[m] - 1;
            if (t >= 0) {
                const float4* a = (const float4*)(inp + (size_t)m * NF);
                const float4* b = (const float4*)(li + (size_t)t * NF);
                float s = 0.0f;
#pragma unroll
                for (int i = 0; i < 2; i++) {
                    float4 av = a[lane + 32 * i], bv = b[lane + 32 * i];
                    float dx = bv.x - av.x, dy = bv.y - av.y;
                    float dz = bv.z - av.z, dw = bv.w - av.w;
                    s += dx * dx + dy * dy + dz * dz + dw * dw;
                }
#pragma unroll
                for (int o = 16; o; o >>= 1) s += __shfl_xor_sync(0xffffffffu, s, o);
                acc += s;
            }
        }
        if (lane == 0) sred[wid] = acc;
        __syncthreads();
        if (tid == 0) {
            float s = 0.0f;
            for (int w = 0; w < 8; w++) s += sred[w];
            g_fc[blockIdx.x] = s;
        }
    }
}

// ---------------------------------------------------------------------------
// Main fused kernel: grid (32, 4) = 128 CTAs, 256 threads.
// Warp grid 2(m) x 4(n); warp tile 64x64 (acc 128 regs, LDSM:MMA = 1:4).
// ---------------------------------------------------------------------------
__global__ void __launch_bounds__(NTHREADS, 1)
main_kernel(const int* __restrict__ roi_label, const int* __restrict__ reid_labels)
{
    extern __shared__ char smem[];
    char* sB = smem + A_BYTES;
    int*   s_lreid = (int*)(smem + SM_META);
    int*   s_lr    = s_lreid + 128;
    int*   s_v2    = s_lr + 128;
    int*   s_pcnt  = s_v2 + 128;
    float* s_red2  = (float*)(smem + SM_RED);    // [4][128]
    int*   s_rlab  = (int*)(smem + SM_RLAB);     // [CHUNK_P]

    const uint32_t sA_a = smem_u32(smem);
    const uint32_t sB_a = smem_u32(sB);

    int tid = threadIdx.x;
    int wid = tid >> 5, lane = tid & 31;
    int qid = lane >> 2, tg = lane & 3;
    int mw = wid >> 2, nw = wid & 3;
    int m0 = blockIdx.x * 128;
    int chunk = blockIdx.y;
    int pbase = chunk * CHUNK_P;

    if (tid < 128) {
        int m = m0 + tid;
        int t = roi_label[m] - 1;
        bool v = (t >= 0);
        int label = v ? t : 0;
        int lreid = reid_labels[label];
        s_lreid[tid] = lreid;
        s_lr[tid] = lreid > 0 ? lreid : 0;
        s_v2[tid] = (v && lreid >= 0) ? 1 : 0;
        s_pcnt[tid] = 0;
    }
    for (int j = tid; j < CHUNK_P; j += NTHREADS) {
        int p = pbase + j;
        s_rlab[j] = (p < NP) ? reid_labels[p] : (int)0x80000000;
    }

    // ---- stage A (f16, 128x256) ----
    {
        const __half* Ain = g_inh + (size_t)m0 * NF;
#pragma unroll
        for (int j = 0; j < 16; j++) {
            int ci = tid + j * NTHREADS;
            int row = ci >> 5, c = ci & 31;
            cp16(sA_a + (uint32_t)(row * AST + c * 8) * 2, Ain + row * NF + c * 8, 16);
        }
    }
    auto issue_B = [&](int i, int buf) {
        int nt = i >> 2, kc = i & 3;
        const __half* lut = (nt < 5) ? g_lih : g_rlh;
        int p0 = pbase + (nt % 5) * 256;
        uint32_t dstBase = sB_a + (uint32_t)buf * B_STAGE;
#pragma unroll
        for (int j = 0; j < 8; j++) {
            int ci = tid + j * NTHREADS;
            int row = ci >> 3, c = ci & 7;
            int p = p0 + row;
            int pc = p < NP ? p : NP - 1;
            cp16(dstBase + (uint32_t)(row * BST + c * 8) * 2,
                 lut + (size_t)pc * NF + kc * 64 + c * 8, (p < NP) ? 16 : 0);
        }
    };
    issue_B(0, 0);
    CP_COMMIT();
    issue_B(1, 1);
    CP_COMMIT();
    issue_B(2, 2);
    CP_COMMIT();

    // ldmatrix lane bases
    uint32_t abase[4];
#pragma unroll
    for (int mf = 0; mf < 4; mf++)
        abase[mf] = sA_a + (uint32_t)((mw * 64 + mf * 16 + (lane & 15)) * AST
                                      + (lane >> 4) * 8) * 2;
    int noff = (lane & 7) + ((lane >> 4) << 3);
    uint32_t bbase = sB_a + (uint32_t)((nw * 64 + noff) * BST + ((lane & 8) ? 8 : 0)) * 2;

    float acc[4][8][4];
    float sacc[8];
#pragma unroll
    for (int q = 0; q < 8; q++) sacc[q] = 0.0f;

    int bufi = 0;
#pragma unroll 1
    for (int i = 0; i < NI; i++) {
        int nt = i >> 2, kc = i & 3;
        if (kc == 0) {
#pragma unroll
            for (int mf = 0; mf < 4; mf++)
#pragma unroll
                for (int nf = 0; nf < 8; nf++)
#pragma unroll
                    for (int r = 0; r < 4; r++) acc[mf][nf][r] = 0.0f;
        }
        CP_WAIT2();
        __syncthreads();

        uint32_t bstage = bbase + (uint32_t)bufi * B_STAGE;
#pragma unroll
        for (int kk = 0; kk < 4; kk++) {
            uint32_t a[4][4], b[16];
            uint32_t akb = (uint32_t)(kc * 4 + kk) * 32;
#pragma unroll
            for (int mf = 0; mf < 4; mf++) ldmx4(a[mf], abase[mf] + akb);
#pragma unroll
            for (int g = 0; g < 4; g++)
                ldmx4(b + g * 4, bstage + (uint32_t)(g * 16 * BST) * 2 + kk * 32);
#pragma unroll
            for (int nf = 0; nf < 8; nf++)
#pragma unroll
                for (int mf = 0; mf < 4; mf++)
                    mma16(acc[mf][nf], a[mf], b[nf * 2], b[nf * 2 + 1]);
        }
        __syncthreads();
        if (i + NSTAGE < NI) issue_B(i + NSTAGE, bufi);
        CP_COMMIT();
        bufi = (bufi == NSTAGE - 1) ? 0 : bufi + 1;

        if (kc == 3) {
            // ---------------- epilogue for tile nt ----------------
            int j0 = (nt % 5) * 256;
            bool inst = (nt < 5);
#pragma unroll
            for (int nf = 0; nf < 8; nf++) {
                int jb = j0 + nw * 64 + nf * 8 + tg * 2;
                int pb = pbase + jb;
                bool ok0 = pb < NP, ok1 = (pb + 1) < NP;
                int rl0 = 0, rl1 = 0;
                if (inst) { rl0 = s_rlab[jb]; rl1 = s_rlab[jb + 1]; }
#pragma unroll
                for (int mf = 0; mf < 4; mf++) {
#pragma unroll
                    for (int h = 0; h < 2; h++) {
                        int lrow = mw * 64 + mf * 16 + h * 8 + qid;
                        int slot = mf * 2 + h;
                        float x0 = acc[mf][nf][h * 2 + 0] * 30.0f;
                        float x1 = acc[mf][nf][h * 2 + 1] * 30.0f;
                        if (inst) {
                            int lre = s_lreid[lrow];
                            if (ok0) {
                                if (rl0 == lre) {
                                    if (s_v2[lrow]) {
                                        int idx = atomicAdd(&s_pcnt[lrow], 1);
                                        if (idx < CAPC)
                                            g_posx[((m0 + lrow) * NCHUNK + chunk) * CAPC + idx] = x0;
                                    }
                                } else sacc[slot] += __expf(x0 - 30.0f);
                            }
                            if (ok1) {
                                if (rl1 == lre) {
                                    if (s_v2[lrow]) {
                                        int idx = atomicAdd(&s_pcnt[lrow], 1);
                                        if (idx < CAPC)
                                            g_posx[((m0 + lrow) * NCHUNK + chunk) * CAPC + idx] = x1;
                                    }
                                } else sacc[slot] += __expf(x1 - 30.0f);
                            }
                        } else {
                            if (ok0) {
                                sacc[slot] += __expf(x0 - 30.0f);
                                if (pb == s_lr[lrow]) g_xt[m0 + lrow] = x0;
                            }
                            if (ok1) {
                                sacc[slot] += __expf(x1 - 30.0f);
                                if (pb + 1 == s_lr[lrow]) g_xt[m0 + lrow] = x1;
                            }
                        }
                    }
                }
            }
            if (nt == 4 || nt == 9) {
                // cross-warp reduction -> one scalar per row
#pragma unroll
                for (int slot = 0; slot < 8; slot++) {
                    float vv = sacc[slot];
                    vv += __shfl_xor_sync(0xffffffffu, vv, 1);
                    vv += __shfl_xor_sync(0xffffffffu, vv, 2);
                    if (tg == 0) {
                        int mf = slot >> 1, h = slot & 1;
                        int lrow = mw * 64 + mf * 16 + h * 8 + qid;
                        s_red2[nw * 128 + lrow] = vv;
                    }
                    sacc[slot] = 0.0f;
                }
                __syncthreads();
                if (tid < 128) {
                    float t = 0.f;
#pragma unroll
                    for (int w = 0; w < 4; w++) t += s_red2[w * 128 + tid];
                    if (nt == 4) g_s_inst[(m0 + tid) * NCHUNK + chunk] = t;
                    else         g_s_reid[(m0 + tid) * NCHUNK + chunk] = t;
                }
            }
        }
    }

    __syncthreads();
    if (tid < 128)
        g_pcnt[(m0 + tid) * NCHUNK + chunk] = s_pcnt[tid];
}

// ---------------------------------------------------------------------------
// Finalize: 32 CTAs x 128 threads, one row per thread; last CTA sums all.
// ---------------------------------------------------------------------------
__global__ void __launch_bounds__(128)
finalize_kernel(const int* __restrict__ roi_label,
                const int* __restrict__ reid_labels, float* __restrict__ out)
{
    __shared__ float sred[4][5];
    __shared__ int s_last;
    int tid = threadIdx.x, wid = tid >> 5, lane = tid & 31;
    int m = blockIdx.x * 128 + tid;

    int t = roi_label[m] - 1;
    bool v = (t >= 0);
    int label = v ? t : 0;
    int lreid = reid_labels[label];
    bool v2 = v && (lreid >= 0);
    int lr = lreid > 0 ? lreid : 0;
    bool v3 = v2 && (lr != IGNORE_INDEX);

    float instS = 0.f, ceS = 0.f;
    if (v2) {
        float s = 0.f;
#pragma unroll
        for (int c = 0; c < NCHUNK; c++) s += g_s_inst[m * NCHUNK + c];
        float lse = (s > 0.f) ? (30.f + logf(s)) : -1e30f;
        int cnt = 0;
        float sum = 0.f;
#pragma unroll
        for (int c = 0; c < NCHUNK; c++) {
            int pc = g_pcnt[m * NCHUNK + c];
            cnt += pc;
            int pl = pc < CAPC ? pc : CAPC;
            for (int q = 0; q < pl; q++)
                sum += log1pf(expf(lse - g_posx[(m * NCHUNK + c) * CAPC + q]));
        }
        instS = sum / fmaxf((float)cnt, 1.f);
        if (v3) {
            float s2 = 0.f;
#pragma unroll
            for (int c = 0; c < NCHUNK; c++) s2 += g_s_reid[m * NCHUNK + c];
            ceS = (30.f + logf(s2)) - g_xt[m];
        }
    }
    float vals[5] = {instS, ceS, v ? 1.f : 0.f, v2 ? 1.f : 0.f, v3 ? 1.f : 0.f};
#pragma unroll
    for (int k = 0; k < 5; k++)
#pragma unroll
        for (int o = 16; o; o >>= 1)
            vals[k] += __shfl_xor_sync(0xffffffffu, vals[k], o);
    if (lane == 0)
        for (int k = 0; k < 5; k++) sred[wid][k] = vals[k];
    __syncthreads();
    if (tid == 0) {
        float tot[5] = {0, 0, 0, 0, 0};
        for (int w = 0; w < 4; w++)
            for (int k = 0; k < 5; k++) tot[k] += sred[w][k];
        for (int k = 0; k < 5; k++) g_part[blockIdx.x][k] = tot[k];
        __threadfence();
        int o = atomicAdd(&g_ticket, 1);
        s_last = (o == NMTILE - 1) ? 1 : 0;
    }
    __syncthreads();
    if (s_last) {
        float fcS = (tid < NCTA) ? g_fc[tid] : 0.f;
#pragma unroll
        for (int o = 16; o; o >>= 1) fcS += __shfl_xor_sync(0xffffffffu, fcS, o);
        if (lane == 0) sred[wid][0] = fcS;
        __syncthreads();
        if (tid == 0) {
            float fc = sred[0][0] + sred[1][0] + sred[2][0] + sred[3][0];
            float tot[5] = {0, 0, 0, 0, 0};
            for (int b = 0; b < NMTILE; b++)
                for (int k = 0; k < 5; k++) tot[k] += g_part[b][k];
            out[0] = fc / (fmaxf(tot[2], 1.f) * (float)NF)
                   + tot[1] / fmaxf(tot[4], 1.f)
                   + tot[0] / fmaxf(tot[3], 1.f);
        }
    }
}

// ---------------------------------------------------------------------------
extern "C" void kernel_launch(void* const* d_in, const int* in_sizes, int n_in,
                              void* d_out, int out_size) {
    const float* inputs      = (const float*)d_in[0];
    const int*   roi_label   = (const int*)d_in[1];
    const float* lut_inst    = (const float*)d_in[2];
    const float* reid_lut    = (const float*)d_in[3];
    const int*   reid_labels = (const int*)d_in[4];
    float* out = (float*)d_out;

    cudaFuncSetAttribute(main_kernel, cudaFuncAttributeMaxDynamicSharedMemorySize,
                         SMEM_TOTAL);

    convert_kernel<<<512, 256>>>(inputs, lut_inst, reid_lut, roi_label);
    main_kernel<<<dim3(NMTILE, NCHUNK), NTHREADS, SMEM_TOTAL>>>(roi_label, reid_labels);
    finalize_kernel<<<NMTILE, 128>>>(roi_label, reid_labels, out);
}

// round 11
// speedup vs baseline: 1.0992x; 1.0992x over previous
#include <cuda_runtime.h>
#include <cuda_fp16.h>
#include <math.h>
#include <stdint.h>

#define NB 4096
#define NF 256
#define NP 5000
#define NPB 20                         // 256-wide p-blocks per LUT
#define UPM 40                         // units per m-tile (20 inst + 20 reid)
#define NUNITS 1280                    // 32 m-tiles * 40
#define NGRID 148
#define NMT 32
#define CAPC 8
#define IGNORE_INDEX 5554
#define BST 72                         // B smem row stride (halfs), 144B
#define A_BYTES 65536                  // 128 x 256 halfs, XOR-swizzled compact
#define B_STAGE (256 * BST * 2)        // 36864
#define NSTAGE 3
#define SM_B    A_BYTES                                // 65536
#define SM_META (SM_B + NSTAGE * B_STAGE)              // 176128
#define SM_RED  (SM_META + 4 * 128 * 4)                // 178176
#define SM_RLAB (SM_RED + 8 * 128 * 4)                 // 182272
#define SMEM_TOTAL (SM_RLAB + 256 * 4)                 // 183296
#define NTHREADS 512

// ---------------- static scratch ----------------
__device__ __align__(16) __half g_inh[NB * NF];
__device__ __align__(16) __half g_lih[NP * NF];
__device__ __align__(16) __half g_rlh[NP * NF];
__device__ float g_s_inst[NB * NPB];
__device__ float g_s_reid[NB * NPB];
__device__ int   g_pcnt[NB * NPB];
__device__ float g_posx[NB * NPB * CAPC];
__device__ float g_xt[NB];
__device__ float g_fc[128];
__device__ float g_part[NMT][5];
__device__ int   g_ticket;

// ---------------- helpers ----------------
__device__ __forceinline__ uint32_t smem_u32(const void* p) {
    uint32_t a;
    asm("{ .reg .u64 t; cvta.to.shared.u64 t, %1; cvt.u32.u64 %0, t; }"
        : "=r"(a) : "l"(p));
    return a;
}
__device__ __forceinline__ void cp16(uint32_t dst, const void* src, int sz) {
    asm volatile("cp.async.cg.shared.global [%0], [%1], 16, %2;"
                 :: "r"(dst), "l"(src), "r"(sz) : "memory");
}
#define CP_COMMIT() asm volatile("cp.async.commit_group;" ::: "memory")
#define CP_WAIT2()  asm volatile("cp.async.wait_group 2;" ::: "memory")
#define CP_WAIT0()  asm volatile("cp.async.wait_group 0;" ::: "memory")

__device__ __forceinline__ void ldmx4(uint32_t* r, uint32_t addr) {
    asm volatile("ldmatrix.sync.aligned.m8n8.x4.shared.b16 {%0,%1,%2,%3}, [%4];"
                 : "=r"(r[0]), "=r"(r[1]), "=r"(r[2]), "=r"(r[3]) : "r"(addr));
}
__device__ __forceinline__ void mma16(float* c, const uint32_t* a,
                                      uint32_t b0, uint32_t b1) {
    asm("mma.sync.aligned.m16n8k16.row.col.f32.f16.f16.f32 "
        "{%0,%1,%2,%3}, {%4,%5,%6,%7}, {%8,%9}, {%0,%1,%2,%3};"
        : "+f"(c[0]), "+f"(c[1]), "+f"(c[2]), "+f"(c[3])
        : "r"(a[0]), "r"(a[1]), "r"(a[2]), "r"(a[3]), "r"(b0), "r"(b1));
}

__device__ __forceinline__ uint2 cvt2(float4 v) {
    uint2 o;
    half2 lo = __floats2half2_rn(v.x, v.y);
    half2 hi = __floats2half2_rn(v.z, v.w);
    o.x = *(uint32_t*)&lo;
    o.y = *(uint32_t*)&hi;
    return o;
}

// ---------------------------------------------------------------------------
// K0: flat grid-stride f32->f16 convert + ticket reset + fc partials.
// ---------------------------------------------------------------------------
#define T0 (NB * NF / 4)
#define T1 (NP * NF / 4)
#define TTOT (T0 + 2 * T1)

__global__ void __launch_bounds__(256)
convert_kernel(const float* __restrict__ inp, const float* __restrict__ li,
               const float* __restrict__ rl, const int* __restrict__ roi_label)
{
    __shared__ float sred[8];
    int tid = threadIdx.x, wid = tid >> 5, lane = tid & 31;
    int idx = blockIdx.x * blockDim.x + tid;
    int stride = blockDim.x * gridDim.x;
    if (blockIdx.x == 0 && tid == 0) g_ticket = 0;

    for (int i = idx; i < TTOT; i += stride) {
        const float4* src;
        uint2* dst;
        int j;
        if (i < T0)           { src = (const float4*)inp; dst = (uint2*)g_inh; j = i; }
        else if (i < T0 + T1) { src = (const float4*)li;  dst = (uint2*)g_lih; j = i - T0; }
        else                  { src = (const float4*)rl;  dst = (uint2*)g_rlh; j = i - T0 - T1; }
        dst[j] = cvt2(src[j]);
    }

    if (blockIdx.x < 128) {
        int m0 = blockIdx.x * 32;
        float acc = 0.0f;
        for (int r = wid; r < 32; r += 8) {
            int m = m0 + r;
            int t = roi_label[m] - 1;
            if (t >= 0) {
                const float4* a = (const float4*)(inp + (size_t)m * NF);
                const float4* b = (const float4*)(li + (size_t)t * NF);
                float s = 0.0f;
#pragma unroll
                for (int i = 0; i < 2; i++) {
                    float4 av = a[lane + 32 * i], bv = b[lane + 32 * i];
                    float dx = bv.x - av.x, dy = bv.y - av.y;
                    float dz = bv.z - av.z, dw = bv.w - av.w;
                    s += dx * dx + dy * dy + dz * dz + dw * dw;
                }
#pragma unroll
                for (int o = 16; o; o >>= 1) s += __shfl_xor_sync(0xffffffffu, s, o);
                acc += s;
            }
        }
        if (lane == 0) sred[wid] = acc;
        __syncthreads();
        if (tid == 0) {
            float s = 0.0f;
            for (int w = 0; w < 8; w++) s += sred[w];
            g_fc[blockIdx.x] = s;
        }
    }
}

// ---------------------------------------------------------------------------
// Main: 148 persistent CTAs, 512 threads. Units = (mt, lut, pblk256), flat
// static partition. Warp grid 2(m) x 8(n), warp tile 64x32 (R9 optimum).
// ---------------------------------------------------------------------------
__global__ void __launch_bounds__(NTHREADS, 1)
main_kernel(const int* __restrict__ roi_label, const int* __restrict__ reid_labels)
{
    extern __shared__ char smem[];
    int*   s_lreid = (int*)(smem + SM_META);
    int*   s_lr    = s_lreid + 128;
    int*   s_v2    = s_lr + 128;
    int*   s_pcnt  = s_v2 + 128;
    float* s_red2  = (float*)(smem + SM_RED);    // [8][128]
    int*   s_rlab  = (int*)(smem + SM_RLAB);     // [256]

    const uint32_t sA_a = smem_u32(smem);
    const uint32_t sB_a = sA_a + SM_B;

    int tid = threadIdx.x;
    int wid = tid >> 5, lane = tid & 31;
    int qid = lane >> 2, tg = lane & 3;
    int mw = wid >> 3, nw = wid & 7;

    int u0 = (int)(((long long)blockIdx.x * NUNITS) / NGRID);
    int u1 = (int)(((long long)(blockIdx.x + 1) * NUNITS) / NGRID);

    // ldmatrix lane bases (A: compact rows of 512B, XOR swizzle on bits 4-6)
    uint32_t ab[4], axor[4];
#pragma unroll
    for (int mf = 0; mf < 4; mf++) {
        int arow = mw * 64 + mf * 16 + (lane & 15);
        ab[mf] = sA_a + (uint32_t)arow * 512;
        axor[mf] = (uint32_t)(arow & 7) << 4;
    }
    uint32_t lp16 = (uint32_t)(lane >> 4) * 16;
    int noff = (lane & 7) + ((lane >> 4) << 3);
    uint32_t bbase = sB_a + (uint32_t)((nw * 32 + noff) * BST + ((lane & 8) ? 8 : 0)) * 2;

    auto issue_it = [&](int git, int buf) {
        int unit = git >> 2, kc = git & 3;
        int w = unit % UPM;
        const __half* lut = (w < NPB) ? g_lih : g_rlh;
        int p0 = (w % NPB) * 256;
        uint32_t dstBase = sB_a + (uint32_t)buf * B_STAGE;
#pragma unroll
        for (int j = 0; j < 4; j++) {
            int ci = tid + j * NTHREADS;
            int row = ci >> 3, c = ci & 7;
            int p = p0 + row;
            int pc = p < NP ? p : NP - 1;
            cp16(dstBase + (uint32_t)(row * BST + c * 8) * 2,
                 lut + (size_t)pc * NF + kc * 64 + c * 8, (p < NP) ? 16 : 0);
        }
    };

    float acc[4][4][4];
    float sacc[8];
#pragma unroll
    for (int q = 0; q < 8; q++) sacc[q] = 0.0f;

    int u = u0;
    while (u < u1) {
        int mt = u / UPM;
        int rEnd = (mt + 1) * UPM;
        if (rEnd > u1) rEnd = u1;
        int m0 = mt * 128;
        int L = (rEnd - u) * 4;
        int g0 = u * 4;

        CP_WAIT0();
        __syncthreads();

        if (tid < 128) {
            int m = m0 + tid;
            int t = roi_label[m] - 1;
            bool v = (t >= 0);
            int label = v ? t : 0;
            int lreid = reid_labels[label];
            s_lreid[tid] = lreid;
            s_lr[tid] = lreid > 0 ? lreid : 0;
            s_v2[tid] = (v && lreid >= 0) ? 1 : 0;
            s_pcnt[tid] = 0;
        }

        // A tile (compact, XOR-swizzled) in prime group 0
        {
            const __half* Ain = g_inh + (size_t)m0 * NF;
#pragma unroll
            for (int j = 0; j < 8; j++) {
                int ci = tid + j * NTHREADS;
                int row = ci >> 5, c = ci & 31;
                cp16(sA_a + (uint32_t)row * 512 + (((uint32_t)c * 16) ^ ((uint32_t)(row & 7) << 4)),
                     Ain + row * NF + c * 8, 16);
            }
        }
        issue_it(g0, 0);
        CP_COMMIT();
        if (L > 1) issue_it(g0 + 1, 1);
        CP_COMMIT();
        if (L > 2) issue_it(g0 + 2, 2);
        CP_COMMIT();

#pragma unroll 1
        for (int li = 0; li < L; li++) {
            int git = g0 + li;
            int kc = git & 3;
            int unit = git >> 2;
            int bufi = li % 3;
            if (kc == 0) {
#pragma unroll
                for (int mf = 0; mf < 4; mf++)
#pragma unroll
                    for (int nf = 0; nf < 4; nf++)
#pragma unroll
                        for (int r = 0; r < 4; r++) acc[mf][nf][r] = 0.0f;
            }
            CP_WAIT2();
            __syncthreads();

            uint32_t bstage = bbase + (uint32_t)bufi * B_STAGE;
#pragma unroll
            for (int kk = 0; kk < 4; kk++) {
                uint32_t a[4][4], b[8];
                uint32_t off = (uint32_t)(kc * 4 + kk) * 32 + lp16;
#pragma unroll
                for (int mf = 0; mf < 4; mf++) ldmx4(a[mf], ab[mf] + (off ^ axor[mf]));
                ldmx4(b,     bstage + kk * 32);
                ldmx4(b + 4, bstage + 16 * BST * 2 + kk * 32);
#pragma unroll
                for (int nf = 0; nf < 4; nf++)
#pragma unroll
                    for (int mf = 0; mf < 4; mf++)
                        mma16(acc[mf][nf], a[mf], b[nf * 2], b[nf * 2 + 1]);
            }
            __syncthreads();
            if (li + 3 < L) issue_it(git + 3, bufi);
            CP_COMMIT();

            int w = unit % UPM;
            bool inst = (w < NPB);
            int pblk = w % NPB;
            int p0 = pblk * 256;

            if (kc == 0) {
                if (tid < 256) {
                    int p = p0 + tid;
                    s_rlab[tid] = (p < NP) ? reid_labels[p] : (int)0x80000000;
                }
            }

            if (kc == 3) {
                // ---------------- epilogue for this unit ----------------
#pragma unroll
                for (int nf = 0; nf < 4; nf++) {
                    int jb = nw * 32 + nf * 8 + tg * 2;
                    int pb = p0 + jb;
                    bool ok0 = pb < NP, ok1 = (pb + 1) < NP;
                    int rl0 = 0, rl1 = 0;
                    if (inst) { rl0 = s_rlab[jb]; rl1 = s_rlab[jb + 1]; }
#pragma unroll
                    for (int mf = 0; mf < 4; mf++) {
#pragma unroll
                        for (int h = 0; h < 2; h++) {
                            int lrow = mw * 64 + mf * 16 + h * 8 + qid;
                            int slot = mf * 2 + h;
                            float x0 = acc[mf][nf][h * 2 + 0] * 30.0f;
                            float x1 = acc[mf][nf][h * 2 + 1] * 30.0f;
                            if (inst) {
                                int lre = s_lreid[lrow];
                                if (ok0) {
                                    if (rl0 == lre) {
                                        if (s_v2[lrow]) {
                                            int idx = atomicAdd(&s_pcnt[lrow], 1);
                                            if (idx < CAPC)
                                                g_posx[((m0 + lrow) * NPB + pblk) * CAPC + idx] = x0;
                                        }
                                    } else sacc[slot] += __expf(x0 - 30.0f);
                                }
                                if (ok1) {
                                    if (rl1 == lre) {
                                        if (s_v2[lrow]) {
                                            int idx = atomicAdd(&s_pcnt[lrow], 1);
                                            if (idx < CAPC)
                                                g_posx[((m0 + lrow) * NPB + pblk) * CAPC + idx] = x1;
                                        }
                                    } else sacc[slot] += __expf(x1 - 30.0f);
                                }
                            } else {
                                if (ok0) {
                                    sacc[slot] += __expf(x0 - 30.0f);
                                    if (pb == s_lr[lrow]) g_xt[m0 + lrow] = x0;
                                }
                                if (ok1) {
                                    sacc[slot] += __expf(x1 - 30.0f);
                                    if (pb + 1 == s_lr[lrow]) g_xt[m0 + lrow] = x1;
                                }
                            }
                        }
                    }
                }
                // cross-warp reduction -> one scalar per row per unit
#pragma unroll
                for (int slot = 0; slot < 8; slot++) {
                    float vv = sacc[slot];
                    vv += __shfl_xor_sync(0xffffffffu, vv, 1);
                    vv += __shfl_xor_sync(0xffffffffu, vv, 2);
                    if (tg == 0) {
                        int mf = slot >> 1, h = slot & 1;
                        int lrow = mw * 64 + mf * 16 + h * 8 + qid;
                        s_red2[nw * 128 + lrow] = vv;
                    }
                    sacc[slot] = 0.0f;
                }
                __syncthreads();
                if (tid < 128) {
                    float t = 0.f;
#pragma unroll
                    for (int ww = 0; ww < 8; ww++) t += s_red2[ww * 128 + tid];
                    if (inst) {
                        g_s_inst[(m0 + tid) * NPB + pblk] = t;
                        g_pcnt[(m0 + tid) * NPB + pblk] = s_pcnt[tid];
                        s_pcnt[tid] = 0;
                    } else {
                        g_s_reid[(m0 + tid) * NPB + pblk] = t;
                    }
                }
            }
        }
        u = rEnd;
    }
}

// ---------------------------------------------------------------------------
// Finalize: 32 CTAs x 128 threads, one row per thread; last CTA sums all.
// ---------------------------------------------------------------------------
__global__ void __launch_bounds__(128)
finalize_kernel(const int* __restrict__ roi_label,
                const int* __restrict__ reid_labels, float* __restrict__ out)
{
    __shared__ float sred[4][5];
    __shared__ int s_last;
    int tid = threadIdx.x, wid = tid >> 5, lane = tid & 31;
    int m = blockIdx.x * 128 + tid;

    int t = roi_label[m] - 1;
    bool v = (t >= 0);
    int label = v ? t : 0;
    int lreid = reid_labels[label];
    bool v2 = v && (lreid >= 0);
    int lr = lreid > 0 ? lreid : 0;
    bool v3 = v2 && (lr != IGNORE_INDEX);

    float instS = 0.f, ceS = 0.f;
    if (v2) {
        float s = 0.f;
#pragma unroll 4
        for (int c = 0; c < NPB; c++) s += g_s_inst[m * NPB + c];
        float lse = (s > 0.f) ? (30.f + logf(s)) : -1e30f;
        int cnt = 0;
        float sum = 0.f;
#pragma unroll 1
        for (int c = 0; c < NPB; c++) {
            int pc = g_pcnt[m * NPB + c];
            cnt += pc;
            int pl = pc < CAPC ? pc : CAPC;
            for (int q = 0; q < pl; q++)
                sum += log1pf(expf(lse - g_posx[(m * NPB + c) * CAPC + q]));
        }
        instS = sum / fmaxf((float)cnt, 1.f);
        if (v3) {
            float s2 = 0.f;
#pragma unroll 4
            for (int c = 0; c < NPB; c++) s2 += g_s_reid[m * NPB + c];
            ceS = (30.f + logf(s2)) - g_xt[m];
        }
    }
    float vals[5] = {instS, ceS, v ? 1.f : 0.f, v2 ? 1.f : 0.f, v3 ? 1.f : 0.f};
#pragma unroll
    for (int k = 0; k < 5; k++)
#pragma unroll
        for (int o = 16; o; o >>= 1)
            vals[k] += __shfl_xor_sync(0xffffffffu, vals[k], o);
    if (lane == 0)
        for (int k = 0; k < 5; k++) sred[wid][k] = vals[k];
    __syncthreads();
    if (tid == 0) {
        float tot[5] = {0, 0, 0, 0, 0};
        for (int w = 0; w < 4; w++)
            for (int k = 0; k < 5; k++) tot[k] += sred[w][k];
        for (int k = 0; k < 5; k++) g_part[blockIdx.x][k] = tot[k];
        __threadfence();
        int o = atomicAdd(&g_ticket, 1);
        s_last = (o == NMT - 1) ? 1 : 0;
    }
    __syncthreads();
    if (s_last) {
        float fcS = (tid < 128) ? g_fc[tid] : 0.f;
#pragma unroll
        for (int o = 16; o; o >>= 1) fcS += __shfl_xor_sync(0xffffffffu, fcS, o);
        if (lane == 0) sred[wid][0] = fcS;
        __syncthreads();
        if (tid == 0) {
            float fc = sred[0][0] + sred[1][0] + sred[2][0] + sred[3][0];
            float tot[5] = {0, 0, 0, 0, 0};
            for (int b = 0; b < NMT; b++)
                for (int k = 0; k < 5; k++) tot[k] += g_part[b][k];
            out[0] = fc / (fmaxf(tot[2], 1.f) * (float)NF)
                   + tot[1] / fmaxf(tot[4], 1.f)
                   + tot[0] / fmaxf(tot[3], 1.f);
        }
    }
}

// ---------------------------------------------------------------------------
extern "C" void kernel_launch(void* const* d_in, const int* in_sizes, int n_in,
                              void* d_out, int out_size) {
    const float* inputs      = (const float*)d_in[0];
    const int*   roi_label   = (const int*)d_in[1];
    const float* lut_inst    = (const float*)d_in[2];
    const float* reid_lut    = (const float*)d_in[3];
    const int*   reid_labels = (const int*)d_in[4];
    float* out = (float*)d_out;

    cudaFuncSetAttribute(main_kernel, cudaFuncAttributeMaxDynamicSharedMemorySize,
                         SMEM_TOTAL);

    convert_kernel<<<512, 256>>>(inputs, lut_inst, reid_lut, roi_label);
    main_kernel<<<NGRID, NTHREADS, SMEM_TOTAL>>>(roi_label, reid_labels);
    finalize_kernel<<<NMT, 128>>>(roi_label, reid_labels, out);
}

// round 12
// speedup vs baseline: 1.2382x; 1.1264x over previous
#include <cuda_runtime.h>
#include <cuda_fp16.h>
#include <math.h>
#include <stdint.h>

#define NB 4096
#define NF 256
#define NP 5000
#define NCHUNK 4
#define CHUNK_P 1280
#define NMTILE 32
#define NCTA (NMTILE * NCHUNK)        // 128
#define CAPC 16
#define IGNORE_INDEX 5554
#define AST 264                       // A smem row stride (halfs), 528B
#define BST 72                        // B smem row stride (halfs), 144B
#define A_BYTES (128 * AST * 2)       // 67584
#define B_STAGE (256 * BST * 2)       // 36864
#define NSTAGE 3
#define SM_META (A_BYTES + NSTAGE * B_STAGE)       // 178176
#define SM_RED  (SM_META + 4 * 128 * 4)            // 180224
#define SM_RLAB (SM_RED + 8 * 128 * 4)             // 184320
#define SMEM_TOTAL (SM_RLAB + CHUNK_P * 4)         // 189440
#define NI 40                         // 10 nt-tiles * 4 k-chunks

// ---------------- static scratch ----------------
__device__ __align__(16) __half g_inh[NB * NF];
__device__ __align__(16) __half g_lih[NP * NF];
__device__ __align__(16) __half g_rlh[NP * NF];
__device__ float g_s_inst[NB * NCHUNK];
__device__ float g_s_reid[NB * NCHUNK];
__device__ int   g_pcnt[NB * NCHUNK];
__device__ float g_posx[NB * NCHUNK * CAPC];
__device__ float g_xt[NB];
__device__ float g_fc[NCTA];
__device__ float g_part[NMTILE][5];
__device__ int   g_ticket;

// ---------------- helpers ----------------
__device__ __forceinline__ uint32_t smem_u32(const void* p) {
    uint32_t a;
    asm("{ .reg .u64 t; cvta.to.shared.u64 t, %1; cvt.u32.u64 %0, t; }"
        : "=r"(a) : "l"(p));
    return a;
}
__device__ __forceinline__ void cp16(uint32_t dst, const void* src, int sz) {
    asm volatile("cp.async.cg.shared.global [%0], [%1], 16, %2;"
                 :: "r"(dst), "l"(src), "r"(sz) : "memory");
}
#define CP_COMMIT() asm volatile("cp.async.commit_group;" ::: "memory")
#define CP_WAIT2()  asm volatile("cp.async.wait_group 2;" ::: "memory")

__device__ __forceinline__ void ldmx4(uint32_t* r, uint32_t addr) {
    asm volatile("ldmatrix.sync.aligned.m8n8.x4.shared.b16 {%0,%1,%2,%3}, [%4];"
                 : "=r"(r[0]), "=r"(r[1]), "=r"(r[2]), "=r"(r[3]) : "r"(addr));
}
__device__ __forceinline__ void mma16(float* c, const uint32_t* a,
                                      uint32_t b0, uint32_t b1) {
    asm("mma.sync.aligned.m16n8k16.row.col.f32.f16.f16.f32 "
        "{%0,%1,%2,%3}, {%4,%5,%6,%7}, {%8,%9}, {%0,%1,%2,%3};"
        : "+f"(c[0]), "+f"(c[1]), "+f"(c[2]), "+f"(c[3])
        : "r"(a[0]), "r"(a[1]), "r"(a[2]), "r"(a[3]), "r"(b0), "r"(b1));
}

__device__ __forceinline__ uint2 cvt2(float4 v) {
    uint2 o;
    half2 lo = __floats2half2_rn(v.x, v.y);
    half2 hi = __floats2half2_rn(v.z, v.w);
    o.x = *(uint32_t*)&lo;
    o.y = *(uint32_t*)&hi;
    return o;
}

// ---------------------------------------------------------------------------
// K0: flat grid-stride f32->f16 convert + ticket reset + fc partials.
// Grid 1184 (8 CTAs/SM) for full warp-slot residency; DRAM-latency bound.
// ---------------------------------------------------------------------------
#define T0 (NB * NF / 4)
#define T1 (NP * NF / 4)
#define TTOT (T0 + 2 * T1)
#define CONV_GRID 1184

__global__ void __launch_bounds__(256)
convert_kernel(const float* __restrict__ inp, const float* __restrict__ li,
               const float* __restrict__ rl, const int* __restrict__ roi_label)
{
    __shared__ float sred[8];
    int tid = threadIdx.x, wid = tid >> 5, lane = tid & 31;
    int idx = blockIdx.x * blockDim.x + tid;
    int stride = blockDim.x * gridDim.x;
    if (blockIdx.x == 0 && tid == 0) g_ticket = 0;

#pragma unroll 2
    for (int i = idx; i < TTOT; i += stride) {
        const float4* src;
        uint2* dst;
        int j;
        if (i < T0)           { src = (const float4*)inp; dst = (uint2*)g_inh; j = i; }
        else if (i < T0 + T1) { src = (const float4*)li;  dst = (uint2*)g_lih; j = i - T0; }
        else                  { src = (const float4*)rl;  dst = (uint2*)g_rlh; j = i - T0 - T1; }
        dst[j] = cvt2(src[j]);
    }

    if (blockIdx.x < NCTA) {
        int m0 = blockIdx.x * (NB / NCTA);
        float acc = 0.0f;
        for (int r = wid; r < NB / NCTA; r += 8) {
            int m = m0 + r;
            int t = roi_label[m] - 1;
            if (t >= 0) {
                const float4* a = (const float4*)(inp + (size_t)m * NF);
                const float4* b = (const float4*)(li + (size_t)t * NF);
                float s = 0.0f;
#pragma unroll
                for (int i = 0; i < 2; i++) {
                    float4 av = a[lane + 32 * i], bv = b[lane + 32 * i];
                    float dx = bv.x - av.x, dy = bv.y - av.y;
                    float dz = bv.z - av.z, dw = bv.w - av.w;
                    s += dx * dx + dy * dy + dz * dz + dw * dw;
                }
#pragma unroll
                for (int o = 16; o; o >>= 1) s += __shfl_xor_sync(0xffffffffu, s, o);
                acc += s;
            }
        }
        if (lane == 0) sred[wid] = acc;
        __syncthreads();
        if (tid == 0) {
            float s = 0.0f;
            for (int w = 0; w < 8; w++) s += sred[w];
            g_fc[blockIdx.x] = s;
        }
    }
}

// ---------------------------------------------------------------------------
// Main fused kernel: grid (32 m-tiles, 4 p-chunks) = 128 CTAs, 512 threads.
// R9 pipeline: 3-stage cp.async, wait_group 2, two syncs per iteration.
// ---------------------------------------------------------------------------
__global__ void __launch_bounds__(512, 1)
main_kernel(const int* __restrict__ roi_label, const int* __restrict__ reid_labels)
{
    extern __shared__ char smem[];
    char* sB = smem + A_BYTES;
    int*   s_lreid = (int*)(smem + SM_META);
    int*   s_lr    = s_lreid + 128;
    int*   s_v2    = s_lr + 128;
    int*   s_pcnt  = s_v2 + 128;
    float* s_red2  = (float*)(smem + SM_RED);    // [8][128]
    int*   s_rlab  = (int*)(smem + SM_RLAB);     // [CHUNK_P]

    const uint32_t sA_a = smem_u32(smem);
    const uint32_t sB_a = smem_u32(sB);

    int tid = threadIdx.x;
    int wid = tid >> 5, lane = tid & 31;
    int qid = lane >> 2, tg = lane & 3;
    int mw = wid >> 3, nw = wid & 7;
    int m0 = blockIdx.x * 128;
    int chunk = blockIdx.y;
    int pbase = chunk * CHUNK_P;

    if (tid < 128) {
        int m = m0 + tid;
        int t = roi_label[m] - 1;
        bool v = (t >= 0);
        int label = v ? t : 0;
        int lreid = reid_labels[label];
        s_lreid[tid] = lreid;
        s_lr[tid] = lreid > 0 ? lreid : 0;
        s_v2[tid] = (v && lreid >= 0) ? 1 : 0;
        s_pcnt[tid] = 0;
    }
    for (int j = tid; j < CHUNK_P; j += 512) {
        int p = pbase + j;
        s_rlab[j] = (p < NP) ? reid_labels[p] : (int)0x80000000;
    }

    // ---- stage A (f16, full 128x256) ----
    {
        const __half* Ain = g_inh + (size_t)m0 * NF;
#pragma unroll
        for (int j = 0; j < 8; j++) {
            int ci = tid + j * 512;
            int row = ci >> 5, c = ci & 31;
            cp16(sA_a + (uint32_t)(row * AST + c * 8) * 2, Ain + row * NF + c * 8, 16);
        }
    }
    auto issue_B = [&](int i, int buf) {
        int nt = i >> 2, kc = i & 3;
        const __half* lut = (nt < 5) ? g_lih : g_rlh;
        int p0 = pbase + (nt % 5) * 256;
        uint32_t dstBase = sB_a + (uint32_t)buf * B_STAGE;
#pragma unroll
        for (int j = 0; j < 4; j++) {
            int ci = tid + j * 512;
            int row = ci >> 3, c = ci & 7;
            int p = p0 + row;
            int pc = p < NP ? p : NP - 1;
            cp16(dstBase + (uint32_t)(row * BST + c * 8) * 2,
                 lut + (size_t)pc * NF + kc * 64 + c * 8, (p < NP) ? 16 : 0);
        }
    };
    issue_B(0, 0);
    CP_COMMIT();
    issue_B(1, 1);
    CP_COMMIT();
    issue_B(2, 2);
    CP_COMMIT();

    // ldmatrix lane bases
    uint32_t abase[4];
#pragma unroll
    for (int mf = 0; mf < 4; mf++)
        abase[mf] = sA_a + (uint32_t)((mw * 64 + mf * 16 + (lane & 15)) * AST
                                      + (lane >> 4) * 8) * 2;
    int noff = (lane & 7) + ((lane >> 4) << 3);
    uint32_t bbase = sB_a + (uint32_t)((nw * 32 + noff) * BST + ((lane & 8) ? 8 : 0)) * 2;

    float acc[4][4][4];
    float sacc[8];
#pragma unroll
    for (int q = 0; q < 8; q++) sacc[q] = 0.0f;

    int bufi = 0;
#pragma unroll 1
    for (int i = 0; i < NI; i++) {
        int nt = i >> 2, kc = i & 3;
        if (kc == 0) {
#pragma unroll
            for (int mf = 0; mf < 4; mf++)
#pragma unroll
                for (int nf = 0; nf < 4; nf++)
#pragma unroll
                    for (int r = 0; r < 4; r++) acc[mf][nf][r] = 0.0f;
        }
        CP_WAIT2();
        __syncthreads();

        uint32_t bstage = bbase + (uint32_t)bufi * B_STAGE;
#pragma unroll
        for (int kk = 0; kk < 4; kk++) {
            uint32_t a[4][4], b[8];
            uint32_t akb = (uint32_t)(kc * 4 + kk) * 32;
#pragma unroll
            for (int mf = 0; mf < 4; mf++) ldmx4(a[mf], abase[mf] + akb);
            ldmx4(b,     bstage + kk * 32);
            ldmx4(b + 4, bstage + 16 * BST * 2 + kk * 32);
#pragma unroll
            for (int nf = 0; nf < 4; nf++)
#pragma unroll
                for (int mf = 0; mf < 4; mf++)
                    mma16(acc[mf][nf], a[mf], b[nf * 2], b[nf * 2 + 1]);
        }
        __syncthreads();
        if (i + NSTAGE < NI) issue_B(i + NSTAGE, bufi);
        CP_COMMIT();
        bufi = (bufi == NSTAGE - 1) ? 0 : bufi + 1;

        if (kc == 3) {
            // ---------------- epilogue for tile nt ----------------
            int j0 = (nt % 5) * 256;
            bool inst = (nt < 5);
#pragma unroll
            for (int nf = 0; nf < 4; nf++) {
                int jb = j0 + nw * 32 + nf * 8 + tg * 2;
                int pb = pbase + jb;
                bool ok0 = pb < NP, ok1 = (pb + 1) < NP;
                int rl0 = 0, rl1 = 0;
                if (inst) { rl0 = s_rlab[jb]; rl1 = s_rlab[jb + 1]; }
#pragma unroll
                for (int mf = 0; mf < 4; mf++) {
#pragma unroll
                    for (int h = 0; h < 2; h++) {
                        int lrow = mw * 64 + mf * 16 + h * 8 + qid;
                        int slot = mf * 2 + h;
                        float x0 = acc[mf][nf][h * 2 + 0] * 30.0f;
                        float x1 = acc[mf][nf][h * 2 + 1] * 30.0f;
                        if (inst) {
                            int lre = s_lreid[lrow];
                            if (ok0) {
                                if (rl0 == lre) {
                                    if (s_v2[lrow]) {
                                        int idx = atomicAdd(&s_pcnt[lrow], 1);
                                        if (idx < CAPC)
                                            g_posx[((m0 + lrow) * NCHUNK + chunk) * CAPC + idx] = x0;
                                    }
                                } else sacc[slot] += __expf(x0 - 30.0f);
                            }
                            if (ok1) {
                                if (rl1 == lre) {
                                    if (s_v2[lrow]) {
                                        int idx = atomicAdd(&s_pcnt[lrow], 1);
                                        if (idx < CAPC)
                                            g_posx[((m0 + lrow) * NCHUNK + chunk) * CAPC + idx] = x1;
                                    }
                                } else sacc[slot] += __expf(x1 - 30.0f);
                            }
                        } else {
                            if (ok0) {
                                sacc[slot] += __expf(x0 - 30.0f);
                                if (pb == s_lr[lrow]) g_xt[m0 + lrow] = x0;
                            }
                            if (ok1) {
                                sacc[slot] += __expf(x1 - 30.0f);
                                if (pb + 1 == s_lr[lrow]) g_xt[m0 + lrow] = x1;
                            }
                        }
                    }
                }
            }
            if (nt == 4 || nt == 9) {
                // cross-warp reduction -> one scalar per row
#pragma unroll
                for (int slot = 0; slot < 8; slot++) {
                    float vv = sacc[slot];
                    vv += __shfl_xor_sync(0xffffffffu, vv, 1);
                    vv += __shfl_xor_sync(0xffffffffu, vv, 2);
                    if (tg == 0) {
                        int mf = slot >> 1, h = slot & 1;
                        int lrow = mw * 64 + mf * 16 + h * 8 + qid;
                        s_red2[nw * 128 + lrow] = vv;
                    }
                    sacc[slot] = 0.0f;
                }
                __syncthreads();
                if (tid < 128) {
                    float t = 0.f;
#pragma unroll
                    for (int w = 0; w < 8; w++) t += s_red2[w * 128 + tid];
                    if (nt == 4) g_s_inst[(m0 + tid) * NCHUNK + chunk] = t;
                    else         g_s_reid[(m0 + tid) * NCHUNK + chunk] = t;
                }
            }
        }
    }

    __syncthreads();
    if (tid < 128)
        g_pcnt[(m0 + tid) * NCHUNK + chunk] = s_pcnt[tid];
}

// ---------------------------------------------------------------------------
// Finalize: 32 CTAs x 128 threads, one row per thread; last CTA sums all.
// ---------------------------------------------------------------------------
__global__ void __launch_bounds__(128)
finalize_kernel(const int* __restrict__ roi_label,
                const int* __restrict__ reid_labels, float* __restrict__ out)
{
    __shared__ float sred[4][5];
    __shared__ int s_last;
    int tid = threadIdx.x, wid = tid >> 5, lane = tid & 31;
    int m = blockIdx.x * 128 + tid;

    int t = roi_label[m] - 1;
    bool v = (t >= 0);
    int label = v ? t : 0;
    int lreid = reid_labels[label];
    bool v2 = v && (lreid >= 0);
    int lr = lreid > 0 ? lreid : 0;
    bool v3 = v2 && (lr != IGNORE_INDEX);

    float instS = 0.f, ceS = 0.f;
    if (v2) {
        float s = 0.f;
#pragma unroll
        for (int c = 0; c < NCHUNK; c++) s += g_s_inst[m * NCHUNK + c];
        float lse = (s > 0.f) ? (30.f + logf(s)) : -1e30f;
        int cnt = 0;
        float sum = 0.f;
#pragma unroll
        for (int c = 0; c < NCHUNK; c++) {
            int pc = g_pcnt[m * NCHUNK + c];
            cnt += pc;
            int pl = pc < CAPC ? pc : CAPC;
            for (int q = 0; q < pl; q++)
                sum += log1pf(expf(lse - g_posx[(m * NCHUNK + c) * CAPC + q]));
        }
        instS = sum / fmaxf((float)cnt, 1.f);
        if (v3) {
            float s2 = 0.f;
#pragma unroll
            for (int c = 0; c < NCHUNK; c++) s2 += g_s_reid[m * NCHUNK + c];
            ceS = (30.f + logf(s2)) - g_xt[m];
        }
    }
    float vals[5] = {instS, ceS, v ? 1.f : 0.f, v2 ? 1.f : 0.f, v3 ? 1.f : 0.f};
#pragma unroll
    for (int k = 0; k < 5; k++)
#pragma unroll
        for (int o = 16; o; o >>= 1)
            vals[k] += __shfl_xor_sync(0xffffffffu, vals[k], o);
    if (lane == 0)
        for (int k = 0; k < 5; k++) sred[wid][k] = vals[k];
    __syncthreads();
    if (tid == 0) {
        float tot[5] = {0, 0, 0, 0, 0};
        for (int w = 0; w < 4; w++)
            for (int k = 0; k < 5; k++) tot[k] += sred[w][k];
        for (int k = 0; k < 5; k++) g_part[blockIdx.x][k] = tot[k];
        __threadfence();
        int o = atomicAdd(&g_ticket, 1);
        s_last = (o == NMTILE - 1) ? 1 : 0;
    }
    __syncthreads();
    if (s_last) {
        float fcS = (tid < NCTA) ? g_fc[tid] : 0.f;
#pragma unroll
        for (int o = 16; o; o >>= 1) fcS += __shfl_xor_sync(0xffffffffu, fcS, o);
        if (lane == 0) sred[wid][0] = fcS;
        __syncthreads();
        if (tid == 0) {
            float fc = sred[0][0] + sred[1][0] + sred[2][0] + sred[3][0];
            float tot[5] = {0, 0, 0, 0, 0};
            for (int b = 0; b < NMTILE; b++)
                for (int k = 0; k < 5; k++) tot[k] += g_part[b][k];
            out[0] = fc / (fmaxf(tot[2], 1.f) * (float)NF)
                   + tot[1] / fmaxf(tot[4], 1.f)
                   + tot[0] / fmaxf(tot[3], 1.f);
        }
    }
}

// ---------------------------------------------------------------------------
extern "C" void kernel_launch(void* const* d_in, const int* in_sizes, int n_in,
                              void* d_out, int out_size) {
    const float* inputs      = (const float*)d_in[0];
    const int*   roi_label   = (const int*)d_in[1];
    const float* lut_inst    = (const float*)d_in[2];
    const float* reid_lut    = (const float*)d_in[3];
    const int*   reid_labels = (const int*)d_in[4];
    float* out = (float*)d_out;

    cudaFuncSetAttribute(main_kernel, cudaFuncAttributeMaxDynamicSharedMemorySize,
                         SMEM_TOTAL);

    convert_kernel<<<CONV_GRID, 256>>>(inputs, lut_inst, reid_lut, roi_label);
    main_kernel<<<dim3(NMTILE, NCHUNK), 512, SMEM_TOTAL>>>(roi_label, reid_labels);
    finalize_kernel<<<NMTILE, 128>>>(roi_label, reid_labels, out);
}